// round 7
// baseline (speedup 1.0000x reference)
#include <cuda_runtime.h>
#include <math.h>

// ---------------------------------------------------------------------------
// Problem constants
// ---------------------------------------------------------------------------
#define N_NODES 50000
#define T_WIN   3
#define E_PER_T 100000
#define HID     128
#define NH      8
#define DK      16
#define M_ROWS  (T_WIN * N_NODES)          // 150000 rows
#define TN      (T_WIN * N_NODES)

// ---------------------------------------------------------------------------
// Device scratch
// ---------------------------------------------------------------------------
__device__ float g_q[(size_t)M_ROWS * HID];
__device__ float g_k[(size_t)M_ROWS * HID];
__device__ float g_v[(size_t)M_ROWS * HID];
__device__ float g_hc[(size_t)TN * HID];        // normalized causal + residual x
__device__ float g_hs[(size_t)TN * HID];        // normalized spurious
__device__ int   g_cnt[T_WIN * N_NODES];        // histogram, then CSR cursor
__device__ int   g_off[T_WIN * (N_NODES + 1)];  // CSR offsets
__device__ int   g_csr[T_WIN * E_PER_T];        // src node ids, grouped by target

// ---------------------------------------------------------------------------
// Packed fp32x2 helpers (B300 FFMA2 path)
// ---------------------------------------------------------------------------
typedef unsigned long long u64;

__device__ __forceinline__ u64 fma2(u64 a, u64 b, u64 c) {
    u64 d;
    asm("fma.rn.f32x2 %0, %1, %2, %3;" : "=l"(d) : "l"(a), "l"(b), "l"(c));
    return d;
}
__device__ __forceinline__ u64 pack2(float lo, float hi) {
    u64 r;
    asm("mov.b64 %0, {%1, %2};" : "=l"(r) : "f"(lo), "f"(hi));
    return r;
}
__device__ __forceinline__ float2 unpack2(u64 v) {
    float2 f;
    asm("mov.b64 {%0, %1}, %2;" : "=f"(f.x), "=f"(f.y) : "l"(v));
    return f;
}

// cp.async 16B
__device__ __forceinline__ void cp16(void* sdst, const void* gsrc) {
    unsigned sa = (unsigned)__cvta_generic_to_shared(sdst);
    asm volatile("cp.async.ca.shared.global [%0], [%1], 16;\n"
                 :: "r"(sa), "l"(gsrc) : "memory");
}
__device__ __forceinline__ void cp_commit() {
    asm volatile("cp.async.commit_group;\n" ::: "memory");
}

// ---------------------------------------------------------------------------
// CSR build: zero -> count -> scan -> fill
// ---------------------------------------------------------------------------
__global__ void zero_cnt_kernel() {
    int i = blockIdx.x * blockDim.x + threadIdx.x;
    if (i < T_WIN * N_NODES) g_cnt[i] = 0;
}

__global__ void count_kernel(const int* __restrict__ ei) {
    int g = blockIdx.x * blockDim.x + threadIdx.x;
    if (g >= T_WIN * E_PER_T) return;
    int t   = g / E_PER_T;
    int idx = g - t * E_PER_T;
    int tar = ei[(size_t)t * 2 * E_PER_T + E_PER_T + idx];
    atomicAdd(&g_cnt[t * N_NODES + tar], 1);
}

// One block (1024 thr) per t: exclusive scan of 50000 counts.
__global__ void __launch_bounds__(1024) scan_kernel() {
    const int t    = blockIdx.x;
    const int tid  = threadIdx.x;
    const int lane = tid & 31;
    const int wid  = tid >> 5;
    __shared__ int wsum[32];
    __shared__ int sbase;
    if (tid == 0) sbase = 0;
    __syncthreads();

    for (int c0 = 0; c0 < N_NODES; c0 += 1024) {
        int i = c0 + tid;
        int v = (i < N_NODES) ? g_cnt[t * N_NODES + i] : 0;
        int incl = v;
        #pragma unroll
        for (int o = 1; o < 32; o <<= 1) {
            int u = __shfl_up_sync(0xFFFFFFFFu, incl, o);
            if (lane >= o) incl += u;
        }
        if (lane == 31) wsum[wid] = incl;
        __syncthreads();
        if (wid == 0) {
            int wv = wsum[lane];
            #pragma unroll
            for (int o = 1; o < 32; o <<= 1) {
                int u = __shfl_up_sync(0xFFFFFFFFu, wv, o);
                if (lane >= o) wv += u;
            }
            wsum[lane] = wv;
        }
        __syncthreads();
        int excl = (wid > 0 ? wsum[wid - 1] : 0) + sbase + incl - v;
        if (i < N_NODES) {
            g_off[t * (N_NODES + 1) + i] = excl;
            g_cnt[t * N_NODES + i]       = excl;   // becomes fill cursor
        }
        __syncthreads();
        if (tid == 0) sbase += wsum[31];
        __syncthreads();
    }
    if (tid == 0) g_off[t * (N_NODES + 1) + N_NODES] = sbase;
}

__global__ void fill_kernel(const int* __restrict__ ei) {
    int g = blockIdx.x * blockDim.x + threadIdx.x;
    if (g >= T_WIN * E_PER_T) return;
    int t   = g / E_PER_T;
    int idx = g - t * E_PER_T;
    int src = ei[(size_t)t * 2 * E_PER_T + idx];
    int tar = ei[(size_t)t * 2 * E_PER_T + E_PER_T + idx];
    int pos = atomicAdd(&g_cnt[t * N_NODES + tar], 1);
    g_csr[(size_t)t * E_PER_T + pos] = src;
}

// ---------------------------------------------------------------------------
// K_qkv: [150000 x 128] @ [128 x 128] + b, packed f32x2 math
// ---------------------------------------------------------------------------
__global__ void __launch_bounds__(256) qkv_kernel(
        const float* __restrict__ x,
        const float* __restrict__ Wq, const float* __restrict__ bq,
        const float* __restrict__ Wk, const float* __restrict__ bk,
        const float* __restrict__ Wv, const float* __restrict__ bv) {
    const float* W; const float* b; float* out;
    if (blockIdx.y == 0)      { W = Wq; b = bq; out = g_q; }
    else if (blockIdx.y == 1) { W = Wk; b = bk; out = g_k; }
    else                      { W = Wv; b = bv; out = g_v; }

    __shared__ float Xs[64][33];
    __shared__ float Ws[32][128];

    const int tid  = threadIdx.x;
    const int m0   = blockIdx.x * 64;
    const int ty   = tid >> 4;
    const int tx   = tid & 15;
    const int row0 = ty * 4;
    const int col0 = tx * 8;

    u64 acc[4][4];
    #pragma unroll
    for (int i = 0; i < 4; i++)
        #pragma unroll
        for (int j = 0; j < 4; j++) acc[i][j] = 0ull;

    for (int kc = 0; kc < 128; kc += 32) {
        #pragma unroll
        for (int l = 0; l < 2; l++) {
            int f4 = tid + l * 256;
            int r  = f4 >> 3;
            int c4 = f4 & 7;
            int grow = m0 + r;
            float4 val = make_float4(0.f, 0.f, 0.f, 0.f);
            if (grow < M_ROWS)
                val = *(const float4*)&x[(size_t)grow * HID + kc + c4 * 4];
            Xs[r][c4 * 4 + 0] = val.x;
            Xs[r][c4 * 4 + 1] = val.y;
            Xs[r][c4 * 4 + 2] = val.z;
            Xs[r][c4 * 4 + 3] = val.w;
        }
        #pragma unroll
        for (int l = 0; l < 4; l++) {
            int f4 = tid + l * 256;
            int r  = f4 >> 5;
            int c4 = f4 & 31;
            *(float4*)&Ws[r][c4 * 4] =
                *(const float4*)&W[(size_t)(kc + r) * HID + c4 * 4];
        }
        __syncthreads();

        #pragma unroll
        for (int k = 0; k < 32; k++) {
            ulonglong2 wb0 = *(const ulonglong2*)&Ws[k][col0];
            ulonglong2 wb1 = *(const ulonglong2*)&Ws[k][col0 + 4];
            #pragma unroll
            for (int i = 0; i < 4; i++) {
                u64 ap = pack2(Xs[row0 + i][k], Xs[row0 + i][k]);
                acc[i][0] = fma2(ap, wb0.x, acc[i][0]);
                acc[i][1] = fma2(ap, wb0.y, acc[i][1]);
                acc[i][2] = fma2(ap, wb1.x, acc[i][2]);
                acc[i][3] = fma2(ap, wb1.y, acc[i][3]);
            }
        }
        __syncthreads();
    }

    #pragma unroll
    for (int i = 0; i < 4; i++) {
        int grow = m0 + row0 + i;
        if (grow < M_ROWS) {
            float o[8];
            #pragma unroll
            for (int j = 0; j < 4; j++) {
                float2 v = unpack2(acc[i][j]);
                o[j * 2]     = v.x + b[col0 + j * 2];
                o[j * 2 + 1] = v.y + b[col0 + j * 2 + 1];
            }
            *(float4*)&out[(size_t)grow * HID + col0]     = make_float4(o[0], o[1], o[2], o[3]);
            *(float4*)&out[(size_t)grow * HID + col0 + 4] = make_float4(o[4], o[5], o[6], o[7]);
        }
    }
}

// ---------------------------------------------------------------------------
// K_agg: warp per (t_tar, node). CSR gather; attention + dual softmax
// aggregation in registers.
// ---------------------------------------------------------------------------
__global__ void __launch_bounds__(256) agg_kernel(const float* __restrict__ x) {
    const int warp = (blockIdx.x * blockDim.x + threadIdx.x) >> 5;
    const int lane = threadIdx.x & 31;
    const int t_tar = blockIdx.y;
    if (warp >= N_NODES) return;
    const int n = warp;

    const size_t rowoff = ((size_t)t_tar * N_NODES + n) * HID + lane * 4;
    const float4 q4 = *(const float4*)&g_q[rowoff];

    float ac0 = 0.f, ac1 = 0.f, ac2 = 0.f, ac3 = 0.f;
    float as0 = 0.f, as1 = 0.f, as2 = 0.f, as3 = 0.f;
    float sc = 0.f, ss = 0.f;

    for (int ts = 0; ts <= t_tar; ts++) {
        const int s0 = g_off[ts * (N_NODES + 1) + n];
        const int s1 = g_off[ts * (N_NODES + 1) + n + 1];
        const int* csr = g_csr + (size_t)ts * E_PER_T;
        const float* kb = g_k + (size_t)ts * N_NODES * HID;
        const float* vb = g_v + (size_t)ts * N_NODES * HID;

        for (int e = s0; e < s1; e++) {
            int src = csr[e];
            size_t so = (size_t)src * HID + lane * 4;
            float4 k4 = *(const float4*)&kb[so];
            float4 v4 = *(const float4*)&vb[so];

            float d = q4.x * k4.x + q4.y * k4.y + q4.z * k4.z + q4.w * k4.w;
            d += __shfl_xor_sync(0xFFFFFFFFu, d, 1);
            d += __shfl_xor_sync(0xFFFFFFFFu, d, 2);
            float a  = d * 0.25f;          // 1/sqrt(16)
            float ec = expf(a);
            float es = expf(-a);
            sc += ec;  ss += es;
            ac0 = fmaf(ec, v4.x, ac0); ac1 = fmaf(ec, v4.y, ac1);
            ac2 = fmaf(ec, v4.z, ac2); ac3 = fmaf(ec, v4.w, ac3);
            as0 = fmaf(es, v4.x, as0); as1 = fmaf(es, v4.y, as1);
            as2 = fmaf(es, v4.z, as2); as3 = fmaf(es, v4.w, as3);
        }
    }

    const float ic = 1.0f / (sc + 1e-16f);
    const float is = 1.0f / (ss + 1e-16f);
    const float4 xv = *(const float4*)&x[rowoff];

    *(float4*)&g_hc[rowoff] = make_float4(fmaf(ac0, ic, xv.x), fmaf(ac1, ic, xv.y),
                                          fmaf(ac2, ic, xv.z), fmaf(ac3, ic, xv.w));
    *(float4*)&g_hs[rowoff] = make_float4(as0 * is, as1 * is, as2 * is, as3 * is);
}

// ---------------------------------------------------------------------------
// K_ffn v6: issue-slot diet. All fma2 operands come from memory pre-packed:
//  - GEMM1: hn stored as DUP u64 pairs (hnd[f][128], 8 KB/warp). LDS.128
//    broadcast gives both dup operands for 2 k-rows. No pack MOVs.
//  - GEMM2: f32x2 packs (j, j+128) PARTIAL SUMS. GELU writes natural pairs
//    gpair[f][j] = (g[j], g[j+128]) (same lane owns both from GEMM1).
//    W2 staged into smem PRE-PAIRED: ws2[j][d] = (W2[j][d], W2[j+128][d]).
//    Inner loop: 2 LDS.128 + 8 LDS.64 + 32 fma2 per j. Epilogue hadd.
// ---------------------------------------------------------------------------
__device__ __forceinline__ float gelu_exact(float v) {
    return 0.5f * v * (1.0f + erff(v * 0.70710678118654752f));
}

// LayerNorm, write DUPLICATED u64 pairs
__device__ __forceinline__ void ln_store_dup(float4 h4, int lane,
                                             float4 lns, float4 lnb,
                                             u64* __restrict__ dst) {
    float s1 = h4.x + h4.y + h4.z + h4.w;
    float s2 = h4.x*h4.x + h4.y*h4.y + h4.z*h4.z + h4.w*h4.w;
    #pragma unroll
    for (int o = 16; o > 0; o >>= 1) {
        s1 += __shfl_xor_sync(0xFFFFFFFFu, s1, o);
        s2 += __shfl_xor_sync(0xFFFFFFFFu, s2, o);
    }
    float mu   = s1 * (1.0f / 128.0f);
    float var  = s2 * (1.0f / 128.0f) - mu * mu;
    float rstd = rsqrtf(var + 1e-5f);

    float h0 = (h4.x - mu) * rstd * lns.x + lnb.x;
    float h1 = (h4.y - mu) * rstd * lns.y + lnb.y;
    float h2 = (h4.z - mu) * rstd * lns.z + lnb.z;
    float h3 = (h4.w - mu) * rstd * lns.w + lnb.w;

    ulonglong2 p01, p23;
    p01.x = pack2(h0, h0); p01.y = pack2(h1, h1);
    p23.x = pack2(h2, h2); p23.y = pack2(h3, h3);
    *(ulonglong2*)&dst[lane * 4]     = p01;
    *(ulonglong2*)&dst[lane * 4 + 2] = p23;
}

__global__ void __launch_bounds__(256, 2) ffn_kernel(
        const float* __restrict__ ln_s, const float* __restrict__ ln_b,
        const float* __restrict__ W1, const float* __restrict__ b1,
        const float* __restrict__ W2, const float* __restrict__ b2,
        float* __restrict__ out) {
    __shared__ __align__(16) u64 sbuf[8][1024];       // 64 KB: hnd then gpair
    __shared__ __align__(16) float ws[2][4096];       // 32 KB: W1 stage / ws2

    const int tid  = threadIdx.x;
    const int wib  = tid >> 5;
    const int lane = tid & 31;
    const int wg   = blockIdx.x * 8 + wib;            // warp id over TN/4
    const bool active = (wg < TN / 4);

    u64* hnd   = sbuf[wib];                           // [8f][128] dup pairs
    u64* gpair = sbuf[wib];                           // [8f][128] (lo,hi) pairs

    const float4 lns = active ? *(const float4*)&ln_s[lane * 4] : make_float4(0,0,0,0);
    const float4 lnb = active ? *(const float4*)&ln_b[lane * 4] : make_float4(0,0,0,0);

    // ---- kick off stage of W1 chunk 0 (16 rows x 256 = 16 KB)
    {
        const float4* g4 = (const float4*)W1;
        #pragma unroll
        for (int t = 0; t < 4; t++)
            cp16(&ws[0][(tid + t * 256) * 4], &g4[tid + t * 256]);
        cp_commit();
    }

    // ---- phase 0: LayerNorm for 8 instances (f = nn*2 + {c,s}), dup pairs
    if (active) {
        #pragma unroll
        for (int nn = 0; nn < 4; nn++) {
            size_t off = ((size_t)wg * 4 + nn) * HID + lane * 4;
            float4 c4 = *(const float4*)&g_hc[off];
            float4 s4 = *(const float4*)&g_hs[off];
            ln_store_dup(c4, lane, lns, lnb, &hnd[(nn * 2 + 0) * 128]);
            ln_store_dup(s4, lane, lns, lnb, &hnd[(nn * 2 + 1) * 128]);
        }
    }
    __syncwarp();

    // ---- GEMM1: lane owns j in {lane*4..+4} and {128+lane*4..+4}
    u64 a1[8][4];
    {
        ulonglong2 bA = *(const ulonglong2*)&b1[lane * 4];
        ulonglong2 bB = *(const ulonglong2*)&b1[128 + lane * 4];
        #pragma unroll
        for (int f = 0; f < 8; f++) {
            a1[f][0] = bA.x; a1[f][1] = bA.y; a1[f][2] = bB.x; a1[f][3] = bB.y;
        }
    }
    #pragma unroll 1
    for (int c = 0; c < 8; c++) {
        if (c < 7) {
            const float4* g4 = (const float4*)(W1 + (size_t)(c + 1) * 16 * 256);
            #pragma unroll
            for (int t = 0; t < 4; t++)
                cp16(&ws[(c + 1) & 1][(tid + t * 256) * 4], &g4[tid + t * 256]);
            cp_commit();
            asm volatile("cp.async.wait_group 1;\n" ::: "memory");
        } else {
            asm volatile("cp.async.wait_group 0;\n" ::: "memory");
        }
        __syncthreads();

        const float* wsb = ws[c & 1];
        #pragma unroll 1
        for (int ii = 0; ii < 16; ii += 2) {
            ulonglong2 wA0 = *(const ulonglong2*)&wsb[ii * 256 + lane * 4];
            ulonglong2 wB0 = *(const ulonglong2*)&wsb[ii * 256 + 128 + lane * 4];
            ulonglong2 wA1 = *(const ulonglong2*)&wsb[(ii + 1) * 256 + lane * 4];
            ulonglong2 wB1 = *(const ulonglong2*)&wsb[(ii + 1) * 256 + 128 + lane * 4];
            const int i = c * 16 + ii;

            #pragma unroll
            for (int f = 0; f < 8; f++) {
                ulonglong2 hp = *(const ulonglong2*)&hnd[f * 128 + i];  // dup(i), dup(i+1)
                a1[f][0] = fma2(hp.x, wA0.x, a1[f][0]);
                a1[f][1] = fma2(hp.x, wA0.y, a1[f][1]);
                a1[f][2] = fma2(hp.x, wB0.x, a1[f][2]);
                a1[f][3] = fma2(hp.x, wB0.y, a1[f][3]);
                a1[f][0] = fma2(hp.y, wA1.x, a1[f][0]);
                a1[f][1] = fma2(hp.y, wA1.y, a1[f][1]);
                a1[f][2] = fma2(hp.y, wB1.x, a1[f][2]);
                a1[f][3] = fma2(hp.y, wB1.y, a1[f][3]);
            }
        }
        __syncthreads();
    }

    // ---- GELU -> gpair[f][j] = (gelu(g[j]), gelu(g[j+128])), j = lane*4+r
    __syncwarp();
    #pragma unroll
    for (int f = 0; f < 8; f++) {
        float2 lo01 = unpack2(a1[f][0]);   // cols 4l, 4l+1
        float2 lo23 = unpack2(a1[f][1]);   // cols 4l+2, 4l+3
        float2 hi01 = unpack2(a1[f][2]);   // cols 128+4l, 128+4l+1
        float2 hi23 = unpack2(a1[f][3]);
        ulonglong2 p01, p23;
        p01.x = pack2(gelu_exact(lo01.x), gelu_exact(hi01.x));
        p01.y = pack2(gelu_exact(lo01.y), gelu_exact(hi01.y));
        p23.x = pack2(gelu_exact(lo23.x), gelu_exact(hi23.x));
        p23.y = pack2(gelu_exact(lo23.y), gelu_exact(hi23.y));
        *(ulonglong2*)&gpair[f * 128 + lane * 4]     = p01;
        *(ulonglong2*)&gpair[f * 128 + lane * 4 + 2] = p23;
    }
    __syncwarp();

    // ---- GEMM2: partial-sum pairs over (j, j+128); W2 staged pre-paired.
    u64 a2[8][4];
    {
        float4 b2v = *(const float4*)&b2[lane * 4];
        u64 i0 = pack2(b2v.x, 0.f), i1 = pack2(b2v.y, 0.f);
        u64 i2 = pack2(b2v.z, 0.f), i3 = pack2(b2v.w, 0.f);
        #pragma unroll
        for (int f = 0; f < 8; f++) {
            a2[f][0] = i0; a2[f][1] = i1; a2[f][2] = i2; a2[f][3] = i3;
        }
    }
    u64* ws2 = (u64*)ws;                               // [32 jj][128 d] pairs
    #pragma unroll 1
    for (int c = 0; c < 4; c++) {
        __syncthreads();
        // stage 32 j-pairs x 128 d, pre-paired (lo=row j, hi=row j+128)
        #pragma unroll
        for (int it = 0; it < 4; it++) {
            int f4  = tid + it * 256;                  // 0..1023
            int jj  = f4 >> 5;                         // 0..31
            int d4  = f4 & 31;                         // 0..31
            int j   = c * 32 + jj;
            float4 lo = *(const float4*)&W2[(size_t)j * 128 + d4 * 4];
            float4 hi = *(const float4*)&W2[(size_t)(j + 128) * 128 + d4 * 4];
            ulonglong2 q01, q23;
            q01.x = pack2(lo.x, hi.x); q01.y = pack2(lo.y, hi.y);
            q23.x = pack2(lo.z, hi.z); q23.y = pack2(lo.w, hi.w);
            *(ulonglong2*)&ws2[jj * 128 + d4 * 4]     = q01;
            *(ulonglong2*)&ws2[jj * 128 + d4 * 4 + 2] = q23;
        }
        __syncthreads();

        #pragma unroll 2
        for (int jj = 0; jj < 32; jj++) {
            ulonglong2 w01 = *(const ulonglong2*)&ws2[jj * 128 + lane * 4];
            ulonglong2 w23 = *(const ulonglong2*)&ws2[jj * 128 + lane * 4 + 2];
            const int j = c * 32 + jj;
            #pragma unroll
            for (int f = 0; f < 8; f++) {
                u64 gp = gpair[f * 128 + j];           // LDS.64 broadcast
                a2[f][0] = fma2(gp, w01.x, a2[f][0]);
                a2[f][1] = fma2(gp, w01.y, a2[f][1]);
                a2[f][2] = fma2(gp, w23.x, a2[f][2]);
                a2[f][3] = fma2(gp, w23.y, a2[f][3]);
            }
        }
    }

    if (!active) return;

    // ---- epilogue: horizontal add of partial-sum pairs, residual, write
    const size_t S = (size_t)TN * HID;
    #pragma unroll
    for (int nn = 0; nn < 4; nn++) {
        size_t off = ((size_t)wg * 4 + nn) * HID + lane * 4;
        float4 c4 = *(const float4*)&g_hc[off];
        float4 s4 = *(const float4*)&g_hs[off];

        float oc[4], os[4];
        #pragma unroll
        for (int r = 0; r < 4; r++) {
            float2 cv = unpack2(a2[nn * 2][r]);
            float2 sv = unpack2(a2[nn * 2 + 1][r]);
            oc[r] = cv.x + cv.y;
            os[r] = sv.x + sv.y;
        }
        oc[0] += c4.x; oc[1] += c4.y; oc[2] += c4.z; oc[3] += c4.w;
        os[0] += s4.x; os[1] += s4.y; os[2] += s4.z; os[3] += s4.w;

        *(float4*)&out[off]         = make_float4(oc[0]+os[0], oc[1]+os[1],
                                                  oc[2]+os[2], oc[3]+os[3]);
        *(float4*)&out[S + off]     = make_float4(oc[0], oc[1], oc[2], oc[3]);
        *(float4*)&out[2*S + off]   = make_float4(os[0], os[1], os[2], os[3]);
    }
}

// ---------------------------------------------------------------------------
// Launch
// ---------------------------------------------------------------------------
extern "C" void kernel_launch(void* const* d_in, const int* in_sizes, int n_in,
                              void* d_out, int out_size) {
    const float* x    = (const float*)d_in[0];
    const int*   ei   = (const int*)  d_in[1];
    const float* Wq   = (const float*)d_in[2];
    const float* bq   = (const float*)d_in[3];
    const float* Wk   = (const float*)d_in[4];
    const float* bk   = (const float*)d_in[5];
    const float* Wv   = (const float*)d_in[6];
    const float* bv   = (const float*)d_in[7];
    const float* ln_s = (const float*)d_in[8];
    const float* ln_b = (const float*)d_in[9];
    const float* W1   = (const float*)d_in[10];
    const float* b1   = (const float*)d_in[11];
    const float* W2   = (const float*)d_in[12];
    const float* b2   = (const float*)d_in[13];
    float* out = (float*)d_out;

    // CSR build (depends only on edge_index)
    zero_cnt_kernel<<<(T_WIN * N_NODES + 255) / 256, 256>>>();
    count_kernel<<<(T_WIN * E_PER_T + 255) / 256, 256>>>(ei);
    scan_kernel<<<T_WIN, 1024>>>();
    fill_kernel<<<(T_WIN * E_PER_T + 255) / 256, 256>>>(ei);

    // QKV projections
    qkv_kernel<<<dim3((M_ROWS + 63) / 64, 3), 256>>>(x, Wq, bq, Wk, bk, Wv, bv);

    // Gather-aggregate
    agg_kernel<<<dim3((N_NODES * 32 + 255) / 256, T_WIN), 256>>>(x);

    // Dual FFN (8 warps x 4 nodes per block)
    ffn_kernel<<<(TN / 4 + 7) / 8, 256>>>(ln_s, ln_b, W1, b1, W2, b2, out);
}

// round 8
// speedup vs baseline: 1.0115x; 1.0115x over previous
#include <cuda_runtime.h>
#include <math.h>

// ---------------------------------------------------------------------------
// Problem constants
// ---------------------------------------------------------------------------
#define N_NODES 50000
#define T_WIN   3
#define E_PER_T 100000
#define HID     128
#define NH      8
#define DK      16
#define M_ROWS  (T_WIN * N_NODES)          // 150000 rows
#define TN      (T_WIN * N_NODES)

// ---------------------------------------------------------------------------
// Device scratch
// ---------------------------------------------------------------------------
__device__ float g_q[(size_t)M_ROWS * HID];
__device__ float g_k[(size_t)M_ROWS * HID];
__device__ float g_v[(size_t)M_ROWS * HID];
__device__ float g_hc[(size_t)TN * HID];        // normalized causal + residual x
__device__ float g_hs[(size_t)TN * HID];        // normalized spurious
__device__ int   g_cnt[T_WIN * N_NODES];        // histogram, then CSR cursor
__device__ int   g_off[T_WIN * (N_NODES + 1)];  // CSR offsets
__device__ int   g_csr[T_WIN * E_PER_T];        // src node ids, grouped by target

// ---------------------------------------------------------------------------
// Packed fp32x2 helpers (B300 FFMA2 path)
// ---------------------------------------------------------------------------
typedef unsigned long long u64;

__device__ __forceinline__ u64 fma2(u64 a, u64 b, u64 c) {
    u64 d;
    asm("fma.rn.f32x2 %0, %1, %2, %3;" : "=l"(d) : "l"(a), "l"(b), "l"(c));
    return d;
}
__device__ __forceinline__ u64 pack2(float lo, float hi) {
    u64 r;
    asm("mov.b64 %0, {%1, %2};" : "=l"(r) : "f"(lo), "f"(hi));
    return r;
}
__device__ __forceinline__ float2 unpack2(u64 v) {
    float2 f;
    asm("mov.b64 {%0, %1}, %2;" : "=f"(f.x), "=f"(f.y) : "l"(v));
    return f;
}

// cp.async 16B
__device__ __forceinline__ void cp16(void* sdst, const void* gsrc) {
    unsigned sa = (unsigned)__cvta_generic_to_shared(sdst);
    asm volatile("cp.async.ca.shared.global [%0], [%1], 16;\n"
                 :: "r"(sa), "l"(gsrc) : "memory");
}
__device__ __forceinline__ void cp_commit() {
    asm volatile("cp.async.commit_group;\n" ::: "memory");
}

// ---------------------------------------------------------------------------
// CSR build: zero -> count -> scan -> fill
// ---------------------------------------------------------------------------
__global__ void zero_cnt_kernel() {
    int i = blockIdx.x * blockDim.x + threadIdx.x;
    if (i < T_WIN * N_NODES) g_cnt[i] = 0;
}

__global__ void count_kernel(const int* __restrict__ ei) {
    int g = blockIdx.x * blockDim.x + threadIdx.x;
    if (g >= T_WIN * E_PER_T) return;
    int t   = g / E_PER_T;
    int idx = g - t * E_PER_T;
    int tar = ei[(size_t)t * 2 * E_PER_T + E_PER_T + idx];
    atomicAdd(&g_cnt[t * N_NODES + tar], 1);
}

// One block (1024 thr) per t: exclusive scan of 50000 counts.
__global__ void __launch_bounds__(1024) scan_kernel() {
    const int t    = blockIdx.x;
    const int tid  = threadIdx.x;
    const int lane = tid & 31;
    const int wid  = tid >> 5;
    __shared__ int wsum[32];
    __shared__ int sbase;
    if (tid == 0) sbase = 0;
    __syncthreads();

    for (int c0 = 0; c0 < N_NODES; c0 += 1024) {
        int i = c0 + tid;
        int v = (i < N_NODES) ? g_cnt[t * N_NODES + i] : 0;
        int incl = v;
        #pragma unroll
        for (int o = 1; o < 32; o <<= 1) {
            int u = __shfl_up_sync(0xFFFFFFFFu, incl, o);
            if (lane >= o) incl += u;
        }
        if (lane == 31) wsum[wid] = incl;
        __syncthreads();
        if (wid == 0) {
            int wv = wsum[lane];
            #pragma unroll
            for (int o = 1; o < 32; o <<= 1) {
                int u = __shfl_up_sync(0xFFFFFFFFu, wv, o);
                if (lane >= o) wv += u;
            }
            wsum[lane] = wv;
        }
        __syncthreads();
        int excl = (wid > 0 ? wsum[wid - 1] : 0) + sbase + incl - v;
        if (i < N_NODES) {
            g_off[t * (N_NODES + 1) + i] = excl;
            g_cnt[t * N_NODES + i]       = excl;   // becomes fill cursor
        }
        __syncthreads();
        if (tid == 0) sbase += wsum[31];
        __syncthreads();
    }
    if (tid == 0) g_off[t * (N_NODES + 1) + N_NODES] = sbase;
}

__global__ void fill_kernel(const int* __restrict__ ei) {
    int g = blockIdx.x * blockDim.x + threadIdx.x;
    if (g >= T_WIN * E_PER_T) return;
    int t   = g / E_PER_T;
    int idx = g - t * E_PER_T;
    int src = ei[(size_t)t * 2 * E_PER_T + idx];
    int tar = ei[(size_t)t * 2 * E_PER_T + E_PER_T + idx];
    int pos = atomicAdd(&g_cnt[t * N_NODES + tar], 1);
    g_csr[(size_t)t * E_PER_T + pos] = src;
}

// ---------------------------------------------------------------------------
// K_qkv: [150000 x 128] @ [128 x 128] + b, packed f32x2 math
// ---------------------------------------------------------------------------
__global__ void __launch_bounds__(256) qkv_kernel(
        const float* __restrict__ x,
        const float* __restrict__ Wq, const float* __restrict__ bq,
        const float* __restrict__ Wk, const float* __restrict__ bk,
        const float* __restrict__ Wv, const float* __restrict__ bv) {
    const float* W; const float* b; float* out;
    if (blockIdx.y == 0)      { W = Wq; b = bq; out = g_q; }
    else if (blockIdx.y == 1) { W = Wk; b = bk; out = g_k; }
    else                      { W = Wv; b = bv; out = g_v; }

    __shared__ float Xs[64][33];
    __shared__ float Ws[32][128];

    const int tid  = threadIdx.x;
    const int m0   = blockIdx.x * 64;
    const int ty   = tid >> 4;
    const int tx   = tid & 15;
    const int row0 = ty * 4;
    const int col0 = tx * 8;

    u64 acc[4][4];
    #pragma unroll
    for (int i = 0; i < 4; i++)
        #pragma unroll
        for (int j = 0; j < 4; j++) acc[i][j] = 0ull;

    for (int kc = 0; kc < 128; kc += 32) {
        #pragma unroll
        for (int l = 0; l < 2; l++) {
            int f4 = tid + l * 256;
            int r  = f4 >> 3;
            int c4 = f4 & 7;
            int grow = m0 + r;
            float4 val = make_float4(0.f, 0.f, 0.f, 0.f);
            if (grow < M_ROWS)
                val = *(const float4*)&x[(size_t)grow * HID + kc + c4 * 4];
            Xs[r][c4 * 4 + 0] = val.x;
            Xs[r][c4 * 4 + 1] = val.y;
            Xs[r][c4 * 4 + 2] = val.z;
            Xs[r][c4 * 4 + 3] = val.w;
        }
        #pragma unroll
        for (int l = 0; l < 4; l++) {
            int f4 = tid + l * 256;
            int r  = f4 >> 5;
            int c4 = f4 & 31;
            *(float4*)&Ws[r][c4 * 4] =
                *(const float4*)&W[(size_t)(kc + r) * HID + c4 * 4];
        }
        __syncthreads();

        #pragma unroll
        for (int k = 0; k < 32; k++) {
            ulonglong2 wb0 = *(const ulonglong2*)&Ws[k][col0];
            ulonglong2 wb1 = *(const ulonglong2*)&Ws[k][col0 + 4];
            #pragma unroll
            for (int i = 0; i < 4; i++) {
                u64 ap = pack2(Xs[row0 + i][k], Xs[row0 + i][k]);
                acc[i][0] = fma2(ap, wb0.x, acc[i][0]);
                acc[i][1] = fma2(ap, wb0.y, acc[i][1]);
                acc[i][2] = fma2(ap, wb1.x, acc[i][2]);
                acc[i][3] = fma2(ap, wb1.y, acc[i][3]);
            }
        }
        __syncthreads();
    }

    #pragma unroll
    for (int i = 0; i < 4; i++) {
        int grow = m0 + row0 + i;
        if (grow < M_ROWS) {
            float o[8];
            #pragma unroll
            for (int j = 0; j < 4; j++) {
                float2 v = unpack2(acc[i][j]);
                o[j * 2]     = v.x + b[col0 + j * 2];
                o[j * 2 + 1] = v.y + b[col0 + j * 2 + 1];
            }
            *(float4*)&out[(size_t)grow * HID + col0]     = make_float4(o[0], o[1], o[2], o[3]);
            *(float4*)&out[(size_t)grow * HID + col0 + 4] = make_float4(o[4], o[5], o[6], o[7]);
        }
    }
}

// ---------------------------------------------------------------------------
// K_agg: warp per (t_tar, node). CSR gather; attention + dual softmax
// aggregation in registers.
// ---------------------------------------------------------------------------
__global__ void __launch_bounds__(256) agg_kernel(const float* __restrict__ x) {
    const int warp = (blockIdx.x * blockDim.x + threadIdx.x) >> 5;
    const int lane = threadIdx.x & 31;
    const int t_tar = blockIdx.y;
    if (warp >= N_NODES) return;
    const int n = warp;

    const size_t rowoff = ((size_t)t_tar * N_NODES + n) * HID + lane * 4;
    const float4 q4 = *(const float4*)&g_q[rowoff];

    float ac0 = 0.f, ac1 = 0.f, ac2 = 0.f, ac3 = 0.f;
    float as0 = 0.f, as1 = 0.f, as2 = 0.f, as3 = 0.f;
    float sc = 0.f, ss = 0.f;

    for (int ts = 0; ts <= t_tar; ts++) {
        const int s0 = g_off[ts * (N_NODES + 1) + n];
        const int s1 = g_off[ts * (N_NODES + 1) + n + 1];
        const int* csr = g_csr + (size_t)ts * E_PER_T;
        const float* kb = g_k + (size_t)ts * N_NODES * HID;
        const float* vb = g_v + (size_t)ts * N_NODES * HID;

        for (int e = s0; e < s1; e++) {
            int src = csr[e];
            size_t so = (size_t)src * HID + lane * 4;
            float4 k4 = *(const float4*)&kb[so];
            float4 v4 = *(const float4*)&vb[so];

            float d = q4.x * k4.x + q4.y * k4.y + q4.z * k4.z + q4.w * k4.w;
            d += __shfl_xor_sync(0xFFFFFFFFu, d, 1);
            d += __shfl_xor_sync(0xFFFFFFFFu, d, 2);
            float a  = d * 0.25f;          // 1/sqrt(16)
            float ec = expf(a);
            float es = expf(-a);
            sc += ec;  ss += es;
            ac0 = fmaf(ec, v4.x, ac0); ac1 = fmaf(ec, v4.y, ac1);
            ac2 = fmaf(ec, v4.z, ac2); ac3 = fmaf(ec, v4.w, ac3);
            as0 = fmaf(es, v4.x, as0); as1 = fmaf(es, v4.y, as1);
            as2 = fmaf(es, v4.z, as2); as3 = fmaf(es, v4.w, as3);
        }
    }

    const float ic = 1.0f / (sc + 1e-16f);
    const float is = 1.0f / (ss + 1e-16f);
    const float4 xv = *(const float4*)&x[rowoff];

    *(float4*)&g_hc[rowoff] = make_float4(fmaf(ac0, ic, xv.x), fmaf(ac1, ic, xv.y),
                                          fmaf(ac2, ic, xv.z), fmaf(ac3, ic, xv.w));
    *(float4*)&g_hs[rowoff] = make_float4(as0 * is, as1 * is, as2 * is, as3 * is);
}

// ---------------------------------------------------------------------------
// K_ffn v7:
//  GEMM1 (as v6): hn stored as DUP u64 pairs; W1 cp.async double-buffered.
//    Per 2 k-rows: 4 W LDS.128 + 8 hn LDS.128 + 32 fma2  (44 issues / 64 fc)
//  GEMM2 (repaired): partial-sum pairs (j, j+128). g pairs read TWO AT A
//    TIME via LDS.128 broadcast; W2 pre-paired into SPLIT arrays ws2a/ws2b
//    with 16B lane stride (conflict-free).
//    Per 2 j-pairs: 4 W LDS.128 + 8 g LDS.128 + 64 fma2  (76 issues / 128 fc)
// ---------------------------------------------------------------------------
__device__ __forceinline__ float gelu_exact(float v) {
    return 0.5f * v * (1.0f + erff(v * 0.70710678118654752f));
}

// LayerNorm, write DUPLICATED u64 pairs
__device__ __forceinline__ void ln_store_dup(float4 h4, int lane,
                                             float4 lns, float4 lnb,
                                             u64* __restrict__ dst) {
    float s1 = h4.x + h4.y + h4.z + h4.w;
    float s2 = h4.x*h4.x + h4.y*h4.y + h4.z*h4.z + h4.w*h4.w;
    #pragma unroll
    for (int o = 16; o > 0; o >>= 1) {
        s1 += __shfl_xor_sync(0xFFFFFFFFu, s1, o);
        s2 += __shfl_xor_sync(0xFFFFFFFFu, s2, o);
    }
    float mu   = s1 * (1.0f / 128.0f);
    float var  = s2 * (1.0f / 128.0f) - mu * mu;
    float rstd = rsqrtf(var + 1e-5f);

    float h0 = (h4.x - mu) * rstd * lns.x + lnb.x;
    float h1 = (h4.y - mu) * rstd * lns.y + lnb.y;
    float h2 = (h4.z - mu) * rstd * lns.z + lnb.z;
    float h3 = (h4.w - mu) * rstd * lns.w + lnb.w;

    ulonglong2 p01, p23;
    p01.x = pack2(h0, h0); p01.y = pack2(h1, h1);
    p23.x = pack2(h2, h2); p23.y = pack2(h3, h3);
    *(ulonglong2*)&dst[lane * 4]     = p01;
    *(ulonglong2*)&dst[lane * 4 + 2] = p23;
}

__global__ void __launch_bounds__(256, 2) ffn_kernel(
        const float* __restrict__ ln_s, const float* __restrict__ ln_b,
        const float* __restrict__ W1, const float* __restrict__ b1,
        const float* __restrict__ W2, const float* __restrict__ b2,
        float* __restrict__ out) {
    __shared__ __align__(16) u64 sbuf[8][1024];   // 64 KB: hnd then gpair
    __shared__ __align__(16) u64 wbuf[4096];      // 32 KB: W1 db stage / ws2a+b

    const int tid  = threadIdx.x;
    const int wib  = tid >> 5;
    const int lane = tid & 31;
    const int wg   = blockIdx.x * 8 + wib;            // warp id over TN/4
    const bool active = (wg < TN / 4);

    u64* hnd   = sbuf[wib];                           // [8f][128] dup pairs
    u64* gpair = sbuf[wib];                           // [8f][128] (lo,hi) pairs
    float (*ws)[4096] = (float (*)[4096])wbuf;        // W1 staging view
    u64* ws2a = wbuf;                                 // [32jj][64] (d0,d1) pairs
    u64* ws2b = wbuf + 2048;                          // [32jj][64] (d2,d3) pairs

    const float4 lns = active ? *(const float4*)&ln_s[lane * 4] : make_float4(0,0,0,0);
    const float4 lnb = active ? *(const float4*)&ln_b[lane * 4] : make_float4(0,0,0,0);

    // ---- kick off stage of W1 chunk 0 (16 rows x 256 = 16 KB)
    {
        const float4* g4 = (const float4*)W1;
        #pragma unroll
        for (int t = 0; t < 4; t++)
            cp16(&ws[0][(tid + t * 256) * 4], &g4[tid + t * 256]);
        cp_commit();
    }

    // ---- phase 0: LayerNorm for 8 instances (f = nn*2 + {c,s}), dup pairs
    if (active) {
        #pragma unroll
        for (int nn = 0; nn < 4; nn++) {
            size_t off = ((size_t)wg * 4 + nn) * HID + lane * 4;
            float4 c4 = *(const float4*)&g_hc[off];
            float4 s4 = *(const float4*)&g_hs[off];
            ln_store_dup(c4, lane, lns, lnb, &hnd[(nn * 2 + 0) * 128]);
            ln_store_dup(s4, lane, lns, lnb, &hnd[(nn * 2 + 1) * 128]);
        }
    }
    __syncwarp();

    // ---- GEMM1: lane owns j in {lane*4..+4} and {128+lane*4..+4}
    u64 a1[8][4];
    {
        ulonglong2 bA = *(const ulonglong2*)&b1[lane * 4];
        ulonglong2 bB = *(const ulonglong2*)&b1[128 + lane * 4];
        #pragma unroll
        for (int f = 0; f < 8; f++) {
            a1[f][0] = bA.x; a1[f][1] = bA.y; a1[f][2] = bB.x; a1[f][3] = bB.y;
        }
    }
    #pragma unroll 1
    for (int c = 0; c < 8; c++) {
        if (c < 7) {
            const float4* g4 = (const float4*)(W1 + (size_t)(c + 1) * 16 * 256);
            #pragma unroll
            for (int t = 0; t < 4; t++)
                cp16(&ws[(c + 1) & 1][(tid + t * 256) * 4], &g4[tid + t * 256]);
            cp_commit();
            asm volatile("cp.async.wait_group 1;\n" ::: "memory");
        } else {
            asm volatile("cp.async.wait_group 0;\n" ::: "memory");
        }
        __syncthreads();

        const float* wsb = ws[c & 1];
        #pragma unroll 1
        for (int ii = 0; ii < 16; ii += 2) {
            ulonglong2 wA0 = *(const ulonglong2*)&wsb[ii * 256 + lane * 4];
            ulonglong2 wB0 = *(const ulonglong2*)&wsb[ii * 256 + 128 + lane * 4];
            ulonglong2 wA1 = *(const ulonglong2*)&wsb[(ii + 1) * 256 + lane * 4];
            ulonglong2 wB1 = *(const ulonglong2*)&wsb[(ii + 1) * 256 + 128 + lane * 4];
            const int i = c * 16 + ii;

            #pragma unroll
            for (int f = 0; f < 8; f++) {
                ulonglong2 hp = *(const ulonglong2*)&hnd[f * 128 + i];  // dup(i), dup(i+1)
                a1[f][0] = fma2(hp.x, wA0.x, a1[f][0]);
                a1[f][1] = fma2(hp.x, wA0.y, a1[f][1]);
                a1[f][2] = fma2(hp.x, wB0.x, a1[f][2]);
                a1[f][3] = fma2(hp.x, wB0.y, a1[f][3]);
                a1[f][0] = fma2(hp.y, wA1.x, a1[f][0]);
                a1[f][1] = fma2(hp.y, wA1.y, a1[f][1]);
                a1[f][2] = fma2(hp.y, wB1.x, a1[f][2]);
                a1[f][3] = fma2(hp.y, wB1.y, a1[f][3]);
            }
        }
        __syncthreads();
    }

    // ---- GELU -> gpair[f][j] = (gelu(g[j]), gelu(g[j+128])), j = lane*4+r
    __syncwarp();
    #pragma unroll
    for (int f = 0; f < 8; f++) {
        float2 lo01 = unpack2(a1[f][0]);   // cols 4l, 4l+1
        float2 lo23 = unpack2(a1[f][1]);   // cols 4l+2, 4l+3
        float2 hi01 = unpack2(a1[f][2]);   // cols 128+4l, 128+4l+1
        float2 hi23 = unpack2(a1[f][3]);
        ulonglong2 p01, p23;
        p01.x = pack2(gelu_exact(lo01.x), gelu_exact(hi01.x));
        p01.y = pack2(gelu_exact(lo01.y), gelu_exact(hi01.y));
        p23.x = pack2(gelu_exact(lo23.x), gelu_exact(hi23.x));
        p23.y = pack2(gelu_exact(lo23.y), gelu_exact(hi23.y));
        *(ulonglong2*)&gpair[f * 128 + lane * 4]     = p01;
        *(ulonglong2*)&gpair[f * 128 + lane * 4 + 2] = p23;
    }
    __syncwarp();

    // ---- GEMM2: partial-sum pairs over (j, j+128); W2 pre-paired, split
    //      arrays for 16B lane stride (bank-conflict-free).
    u64 a2[8][4];
    {
        float4 b2v = *(const float4*)&b2[lane * 4];
        u64 i0 = pack2(b2v.x, 0.f), i1 = pack2(b2v.y, 0.f);
        u64 i2 = pack2(b2v.z, 0.f), i3 = pack2(b2v.w, 0.f);
        #pragma unroll
        for (int f = 0; f < 8; f++) {
            a2[f][0] = i0; a2[f][1] = i1; a2[f][2] = i2; a2[f][3] = i3;
        }
    }
    #pragma unroll 1
    for (int c = 0; c < 4; c++) {
        __syncthreads();
        // stage 32 j-pairs x 128 d, pre-paired (lo=row j, hi=row j+128)
        #pragma unroll
        for (int it = 0; it < 4; it++) {
            int f4  = tid + it * 256;                  // 0..1023
            int jj  = f4 >> 5;                         // 0..31
            int d4  = f4 & 31;                         // 0..31
            int j   = c * 32 + jj;
            float4 lo = *(const float4*)&W2[(size_t)j * 128 + d4 * 4];
            float4 hi = *(const float4*)&W2[(size_t)(j + 128) * 128 + d4 * 4];
            ulonglong2 q01, q23;
            q01.x = pack2(lo.x, hi.x); q01.y = pack2(lo.y, hi.y);
            q23.x = pack2(lo.z, hi.z); q23.y = pack2(lo.w, hi.w);
            *(ulonglong2*)&ws2a[jj * 64 + d4 * 2] = q01;   // (d0,d1)
            *(ulonglong2*)&ws2b[jj * 64 + d4 * 2] = q23;   // (d2,d3)
        }
        __syncthreads();

        #pragma unroll 2
        for (int jj = 0; jj < 32; jj += 2) {
            ulonglong2 wa0 = *(const ulonglong2*)&ws2a[jj * 64 + lane * 2];
            ulonglong2 wb0 = *(const ulonglong2*)&ws2b[jj * 64 + lane * 2];
            ulonglong2 wa1 = *(const ulonglong2*)&ws2a[(jj + 1) * 64 + lane * 2];
            ulonglong2 wb1 = *(const ulonglong2*)&ws2b[(jj + 1) * 64 + lane * 2];
            const int j = c * 32 + jj;
            #pragma unroll
            for (int f = 0; f < 8; f++) {
                ulonglong2 gp = *(const ulonglong2*)&gpair[f * 128 + j]; // jj, jj+1
                a2[f][0] = fma2(gp.x, wa0.x, a2[f][0]);
                a2[f][1] = fma2(gp.x, wa0.y, a2[f][1]);
                a2[f][2] = fma2(gp.x, wb0.x, a2[f][2]);
                a2[f][3] = fma2(gp.x, wb0.y, a2[f][3]);
                a2[f][0] = fma2(gp.y, wa1.x, a2[f][0]);
                a2[f][1] = fma2(gp.y, wa1.y, a2[f][1]);
                a2[f][2] = fma2(gp.y, wb1.x, a2[f][2]);
                a2[f][3] = fma2(gp.y, wb1.y, a2[f][3]);
            }
        }
    }

    if (!active) return;

    // ---- epilogue: horizontal add of partial-sum pairs, residual, write
    const size_t S = (size_t)TN * HID;
    #pragma unroll
    for (int nn = 0; nn < 4; nn++) {
        size_t off = ((size_t)wg * 4 + nn) * HID + lane * 4;
        float4 c4 = *(const float4*)&g_hc[off];
        float4 s4 = *(const float4*)&g_hs[off];

        float oc[4], os[4];
        #pragma unroll
        for (int r = 0; r < 4; r++) {
            float2 cv = unpack2(a2[nn * 2][r]);
            float2 sv = unpack2(a2[nn * 2 + 1][r]);
            oc[r] = cv.x + cv.y;
            os[r] = sv.x + sv.y;
        }
        oc[0] += c4.x; oc[1] += c4.y; oc[2] += c4.z; oc[3] += c4.w;
        os[0] += s4.x; os[1] += s4.y; os[2] += s4.z; os[3] += s4.w;

        *(float4*)&out[off]         = make_float4(oc[0]+os[0], oc[1]+os[1],
                                                  oc[2]+os[2], oc[3]+os[3]);
        *(float4*)&out[S + off]     = make_float4(oc[0], oc[1], oc[2], oc[3]);
        *(float4*)&out[2*S + off]   = make_float4(os[0], os[1], os[2], os[3]);
    }
}

// ---------------------------------------------------------------------------
// Launch
// ---------------------------------------------------------------------------
extern "C" void kernel_launch(void* const* d_in, const int* in_sizes, int n_in,
                              void* d_out, int out_size) {
    const float* x    = (const float*)d_in[0];
    const int*   ei   = (const int*)  d_in[1];
    const float* Wq   = (const float*)d_in[2];
    const float* bq   = (const float*)d_in[3];
    const float* Wk   = (const float*)d_in[4];
    const float* bk   = (const float*)d_in[5];
    const float* Wv   = (const float*)d_in[6];
    const float* bv   = (const float*)d_in[7];
    const float* ln_s = (const float*)d_in[8];
    const float* ln_b = (const float*)d_in[9];
    const float* W1   = (const float*)d_in[10];
    const float* b1   = (const float*)d_in[11];
    const float* W2   = (const float*)d_in[12];
    const float* b2   = (const float*)d_in[13];
    float* out = (float*)d_out;

    // CSR build (depends only on edge_index)
    zero_cnt_kernel<<<(T_WIN * N_NODES + 255) / 256, 256>>>();
    count_kernel<<<(T_WIN * E_PER_T + 255) / 256, 256>>>(ei);
    scan_kernel<<<T_WIN, 1024>>>();
    fill_kernel<<<(T_WIN * E_PER_T + 255) / 256, 256>>>(ei);

    // QKV projections
    qkv_kernel<<<dim3((M_ROWS + 63) / 64, 3), 256>>>(x, Wq, bq, Wk, bk, Wv, bv);

    // Gather-aggregate
    agg_kernel<<<dim3((N_NODES * 32 + 255) / 256, T_WIN), 256>>>(x);

    // Dual FFN (8 warps x 4 nodes per block)
    ffn_kernel<<<(TN / 4 + 7) / 8, 256>>>(ln_s, ln_b, W1, b1, W2, b2, out);
}